// round 6
// baseline (speedup 1.0000x reference)
#include <cuda_runtime.h>
#include <cuda_bf16.h>
#include <cstdint>

#define DI    2048
#define LSEQ  512
#define BT    1024          // B*L
#define GRIDN 148
#define UC_S  8             // units per block with SMEM-cached weights
#define NREG_MAX 6          // max units per block with register-cached weights

// ------------------------- device scratch -------------------------
__device__ float g_xz[(size_t)BT * 4096];      // [bt][x_in(2048) | z(2048)]
__device__ float g_xconv[(size_t)BT * DI];
__device__ float g_gi[(size_t)BT * 6144];
__device__ float g_basedt[(size_t)BT * DI];
__device__ float g_ygated[(size_t)BT * DI];
__device__ float g_xdbl[(size_t)BT * 96];
__device__ float g_bdual[BT * 16];
__device__ float g_scaling[BT];
__device__ float g_spart[(size_t)BT * GRIDN];
__device__ float g_h[2][2 * DI];
__device__ unsigned g_flag[GRIDN];

__device__ __forceinline__ float sigmf_(float x) { return 1.f / (1.f + expf(-x)); }
__device__ __forceinline__ float softplusf_(float x) {
    return fmaxf(x, 0.f) + log1pf(expf(-fabsf(x)));
}

// ------------------------- init -------------------------
__global__ void k_init() {
    int i = blockIdx.x * 256 + threadIdx.x;
    if (i < 2 * DI) g_h[1][i] = 0.f;      // h(-1) read buffer
    if (i < GRIDN) g_flag[i] = 0u;
}

// ------------------- 128x128 tiled GEMM: C = act(A @ W^T [+bias]) ----------
// Requires M,N % 128 == 0, K % 16 == 0.
template <int ACT>
__global__ void __launch_bounds__(256) k_gemm128(
    const float* __restrict__ A, int lda,
    const float* __restrict__ W, int ldw,
    const float* __restrict__ bias,
    float* __restrict__ C, int ldc, int K)
{
    __shared__ float As[16][132];
    __shared__ float Bs[16][132];
    int tid = threadIdx.x;
    int bm = blockIdx.y * 128, bn = blockIdx.x * 128;
    int lr = tid >> 2;               // 0..63
    int lc = (tid & 3) << 2;         // 0,4,8,12
    int ty = tid >> 4, tx = tid & 15;
    const float* A0 = A + (size_t)(bm + lr) * lda;
    const float* A1 = A + (size_t)(bm + lr + 64) * lda;
    const float* W0 = W + (size_t)(bn + lr) * ldw;
    const float* W1 = W + (size_t)(bn + lr + 64) * ldw;
    float acc[8][8] = {};
    for (int k0 = 0; k0 < K; k0 += 16) {
        float4 a0 = *(const float4*)(A0 + k0 + lc);
        float4 a1 = *(const float4*)(A1 + k0 + lc);
        float4 w0 = *(const float4*)(W0 + k0 + lc);
        float4 w1 = *(const float4*)(W1 + k0 + lc);
        __syncthreads();
        As[lc+0][lr] = a0.x; As[lc+1][lr] = a0.y; As[lc+2][lr] = a0.z; As[lc+3][lr] = a0.w;
        As[lc+0][lr+64] = a1.x; As[lc+1][lr+64] = a1.y; As[lc+2][lr+64] = a1.z; As[lc+3][lr+64] = a1.w;
        Bs[lc+0][lr] = w0.x; Bs[lc+1][lr] = w0.y; Bs[lc+2][lr] = w0.z; Bs[lc+3][lr] = w0.w;
        Bs[lc+0][lr+64] = w1.x; Bs[lc+1][lr+64] = w1.y; Bs[lc+2][lr+64] = w1.z; Bs[lc+3][lr+64] = w1.w;
        __syncthreads();
        #pragma unroll
        for (int kk = 0; kk < 16; kk++) {
            float af[8], bf[8];
            *(float4*)af       = *(const float4*)&As[kk][ty * 8];
            *(float4*)(af + 4) = *(const float4*)&As[kk][ty * 8 + 4];
            *(float4*)bf       = *(const float4*)&Bs[kk][tx * 8];
            *(float4*)(bf + 4) = *(const float4*)&Bs[kk][tx * 8 + 4];
            #pragma unroll
            for (int i = 0; i < 8; i++)
                #pragma unroll
                for (int j = 0; j < 8; j++)
                    acc[i][j] = fmaf(af[i], bf[j], acc[i][j]);
        }
    }
    #pragma unroll
    for (int i = 0; i < 8; i++) {
        size_t row = (size_t)(bm + ty * 8 + i) * ldc;
        #pragma unroll
        for (int j = 0; j < 8; j++) {
            int col = bn + tx * 8 + j;
            float v = acc[i][j];
            if (ACT == 1) v += bias[col];
            C[row + col] = v;
        }
    }
}

// --------------- small generic GEMM (64x64): C = act(A @ W^T [+bias]) ------
// ACT: 0 none, 1 +bias, 2 softplus(acc + 2*bias)
template <int ACT>
__global__ void __launch_bounds__(256) k_gemm(
    const float* __restrict__ A, int lda,
    const float* __restrict__ W, int ldw,
    const float* __restrict__ bias,
    float* __restrict__ C, int ldc, int N, int K)
{
    __shared__ float As[16][68];
    __shared__ float Bs[16][68];
    int tid = threadIdx.x;
    int bm = blockIdx.y * 64, bn = blockIdx.x * 64;
    int tx = tid & 15, ty = tid >> 4;
    int lr = tid >> 2, lk = (tid & 3) * 4;
    float acc[4][4] = {};
    for (int k0 = 0; k0 < K; k0 += 16) {
        float4 av = *(const float4*)(A + (size_t)(bm + lr) * lda + k0 + lk);
        float4 wv = make_float4(0.f, 0.f, 0.f, 0.f);
        if (bn + lr < N) wv = *(const float4*)(W + (size_t)(bn + lr) * ldw + k0 + lk);
        __syncthreads();
        As[lk][lr] = av.x; As[lk+1][lr] = av.y; As[lk+2][lr] = av.z; As[lk+3][lr] = av.w;
        Bs[lk][lr] = wv.x; Bs[lk+1][lr] = wv.y; Bs[lk+2][lr] = wv.z; Bs[lk+3][lr] = wv.w;
        __syncthreads();
        #pragma unroll
        for (int kk = 0; kk < 16; kk++) {
            float4 a = *(const float4*)&As[kk][ty * 4];
            float4 b = *(const float4*)&Bs[kk][tx * 4];
            float ar[4] = {a.x, a.y, a.z, a.w};
            float br[4] = {b.x, b.y, b.z, b.w};
            #pragma unroll
            for (int i = 0; i < 4; i++)
                #pragma unroll
                for (int j = 0; j < 4; j++)
                    acc[i][j] = fmaf(ar[i], br[j], acc[i][j]);
        }
    }
    #pragma unroll
    for (int i = 0; i < 4; i++) {
        int row = bm + ty * 4 + i;
        #pragma unroll
        for (int j = 0; j < 4; j++) {
            int col = bn + tx * 4 + j;
            if (col < N) {
                float v = acc[i][j];
                if (ACT == 1) v += bias[col];
                if (ACT == 2) { v += 2.f * bias[col]; v = softplusf_(v); }
                C[(size_t)row * ldc + col] = v;
            }
        }
    }
}

// ------------------------- causal conv + silu -------------------------
__global__ void __launch_bounds__(256) k_conv(
    const float* __restrict__ cw, const float* __restrict__ cb)
{
    int idx = blockIdx.x * 256 + threadIdx.x;     // over BT*DI
    int d = idx & (DI - 1);
    int bt = idx >> 11;
    int t = bt & (LSEQ - 1);
    float acc = cb[d];
    #pragma unroll
    for (int k = 0; k < 4; k++) {
        int tt = t + k - 3;
        if (tt >= 0)
            acc = fmaf(g_xz[(size_t)(bt + k - 3) * 4096 + d], cw[d * 4 + k], acc);
    }
    g_xconv[(size_t)bt * DI + d] = acc * sigmf_(acc);   // silu
}

// ------------------------- persistent GRU v2 -------------------------
// 148 blocks x 256 threads. Each warp owns a 256-wide k-slice of h (in regs).
// 8 units' weights (24 rows) in SMEM fp32; remaining <=6 units (18 rows) in
// registers (loaded once). Weights read exactly once per step. Flag barrier.
__global__ void __launch_bounds__(256, 1) k_gru(
    const float* __restrict__ whh, const float* __restrict__ bhh,
    const float* __restrict__ wtw)
{
    extern __shared__ float sm[];
    float* sw = sm;                      // UC_S*3*DI fp32 weight rows
    float* ps = sm + UC_S * 3 * DI;      // 84*8 partials [row2][warp]
    float* sc = ps + 84 * 8;             // 32 scaling partials

    int bid = blockIdx.x, tid = threadIdx.x;
    int lane = tid & 31, wid = tid >> 5;
    int ustart = bid * 13 + min(bid, 124);
    int ucnt = 13 + (bid < 124 ? 1 : 0);
    int nreg3 = (ucnt - UC_S) * 3;       // 15 or 18 register rows
    int kb = wid * 256 + lane * 4;       // this lane's chunk0 base (chunk1 = +128)

    // preload SMEM weight rows: r = u*3+g, u in [0,8)
    for (int r = 0; r < UC_S * 3; r++) {
        int u = r / 3, g = r - u * 3;
        const float4* src = (const float4*)(whh + ((size_t)g * DI + ustart + u) * DI);
        float4* dst = (float4*)(sw + r * DI);
        for (int i = tid; i < DI / 4; i += 256) dst[i] = src[i];
    }
    // preload register weight rows: rr -> u = UC_S + rr/3, g = rr%3
    float wr[18][8] = {};
    #pragma unroll
    for (int rr = 0; rr < 18; rr++) {
        if (rr < nreg3) {
            int u = UC_S + rr / 3, g = rr - (rr / 3) * 3;
            const float* base = whh + ((size_t)g * DI + ustart + u) * DI;
            float4 c0 = *(const float4*)(base + kb);
            float4 c1 = *(const float4*)(base + kb + 128);
            wr[rr][0] = c0.x; wr[rr][1] = c0.y; wr[rr][2] = c0.z; wr[rr][3] = c0.w;
            wr[rr][4] = c1.x; wr[rr][5] = c1.y; wr[rr][6] = c1.z; wr[rr][7] = c1.w;
        }
    }
    // epilogue constants (one thread per (u,b))
    float eb_r = 0.f, eb_z = 0.f, eb_n = 0.f, ewt = 0.f;
    if (tid < 2 * ucnt) {
        int d = ustart + (tid >> 1);
        eb_r = bhh[d]; eb_z = bhh[2048 + d]; eb_n = bhh[4096 + d]; ewt = wtw[d];
    }
    __syncthreads();

    for (int t = 0; t < LSEQ; t++) {
        if (t > 0) {
            if (tid < GRIDN) {
                volatile unsigned* f = (volatile unsigned*)&g_flag[tid];
                while (*f < (unsigned)t) { }
            }
            __syncthreads();
        }
        const float* hp = g_h[(t + 1) & 1];

        // load this warp's h slice into registers
        float h0[8], h1[8];
        {
            float4 a = __ldcg((const float4*)(hp + kb));
            float4 b = __ldcg((const float4*)(hp + kb + 128));
            h0[0]=a.x; h0[1]=a.y; h0[2]=a.z; h0[3]=a.w;
            h0[4]=b.x; h0[5]=b.y; h0[6]=b.z; h0[7]=b.w;
            float4 c = __ldcg((const float4*)(hp + DI + kb));
            float4 d4 = __ldcg((const float4*)(hp + DI + kb + 128));
            h1[0]=c.x; h1[1]=c.y; h1[2]=c.z; h1[3]=c.w;
            h1[4]=d4.x; h1[5]=d4.y; h1[6]=d4.z; h1[7]=d4.w;
        }
        // epilogue prefetch (hidden under dot compute)
        float gi_r = 0.f, gi_z = 0.f, gi_n = 0.f, hprev = 0.f;
        if (tid < 2 * ucnt) {
            int u = tid >> 1, b = tid & 1, d = ustart + u;
            size_t gib = ((size_t)(b * LSEQ + t)) * 6144 + d;
            gi_r = __ldg(&g_gi[gib]);
            gi_z = __ldg(&g_gi[gib + 2048]);
            gi_n = __ldg(&g_gi[gib + 4096]);
            hprev = __ldcg(&hp[b * DI + d]);
        }

        // --- dot products: SMEM rows ---
        bool lo = lane < 16;
        for (int r = 0; r < UC_S * 3; r++) {
            const float* w = sw + r * DI + kb;
            float4 w0 = *(const float4*)w;
            float4 w1 = *(const float4*)(w + 128);
            float a0, a1;
            a0  = w0.x * h0[0]; a1  = w0.x * h1[0];
            a0 = fmaf(w0.y, h0[1], a0); a1 = fmaf(w0.y, h1[1], a1);
            a0 = fmaf(w0.z, h0[2], a0); a1 = fmaf(w0.z, h1[2], a1);
            a0 = fmaf(w0.w, h0[3], a0); a1 = fmaf(w0.w, h1[3], a1);
            a0 = fmaf(w1.x, h0[4], a0); a1 = fmaf(w1.x, h1[4], a1);
            a0 = fmaf(w1.y, h0[5], a0); a1 = fmaf(w1.y, h1[5], a1);
            a0 = fmaf(w1.z, h0[6], a0); a1 = fmaf(w1.z, h1[6], a1);
            a0 = fmaf(w1.w, h0[7], a0); a1 = fmaf(w1.w, h1[7], a1);
            // fold both accs into one butterfly: lanes<16 reduce a0, lanes>=16 reduce a1
            float v = (lo ? a0 : a1) + __shfl_xor_sync(0xffffffffu, lo ? a1 : a0, 16);
            v += __shfl_xor_sync(0xffffffffu, v, 8);
            v += __shfl_xor_sync(0xffffffffu, v, 4);
            v += __shfl_xor_sync(0xffffffffu, v, 2);
            v += __shfl_xor_sync(0xffffffffu, v, 1);
            if ((lane & 15) == 0) ps[(r * 2 + (lane >> 4)) * 8 + wid] = v;
        }
        // --- dot products: register rows ---
        #pragma unroll
        for (int rr = 0; rr < 18; rr++) {
            if (rr < nreg3) {
                float a0 = 0.f, a1 = 0.f;
                #pragma unroll
                for (int j = 0; j < 8; j++) {
                    a0 = fmaf(wr[rr][j], h0[j], a0);
                    a1 = fmaf(wr[rr][j], h1[j], a1);
                }
                float v = (lo ? a0 : a1) + __shfl_xor_sync(0xffffffffu, lo ? a1 : a0, 16);
                v += __shfl_xor_sync(0xffffffffu, v, 8);
                v += __shfl_xor_sync(0xffffffffu, v, 4);
                v += __shfl_xor_sync(0xffffffffu, v, 2);
                v += __shfl_xor_sync(0xffffffffu, v, 1);
                if ((lane & 15) == 0) ps[((UC_S * 3 + rr) * 2 + (lane >> 4)) * 8 + wid] = v;
            }
        }
        __syncthreads();

        // --- epilogue: one thread per (u,b) ---
        if (tid < 2 * ucnt) {
            int u = tid >> 1, b = tid & 1, d = ustart + u;
            int r0 = (u * 3 + 0) * 2 + b;
            int r1 = (u * 3 + 1) * 2 + b;
            int r2 = (u * 3 + 2) * 2 + b;
            float hr = 0.f, hz = 0.f, hn = 0.f;
            #pragma unroll
            for (int w = 0; w < 8; w++) {
                hr += ps[r0 * 8 + w];
                hz += ps[r1 * 8 + w];
                hn += ps[r2 * 8 + w];
            }
            float r  = sigmf_(gi_r + hr + eb_r);
            float uz = sigmf_(gi_z + hz + eb_z);
            float nn = tanhf (gi_n + r * (hn + eb_n));
            float hnew = (1.f - uz) * nn + uz * hprev;
            __stcg(&g_h[t & 1][b * DI + d], hnew);
            sc[tid] = hnew * ewt;
            __threadfence();
        }
        __syncthreads();
        if (tid < 2) {
            float s = 0.f;
            for (int u = 0; u < ucnt; u++) s += sc[u * 2 + tid];
            g_spart[((size_t)(tid * LSEQ + t)) * GRIDN + bid] = s;
        }
        if (tid == 0) __stcg(&g_flag[bid], (unsigned)(t + 1));
    }
}

// ------------------------- scaling reduce (deterministic) -------------------
__global__ void k_scale(const float* __restrict__ wtb, float* __restrict__ dout,
                        int has_tail)
{
    int bt = blockIdx.x * blockDim.x + threadIdx.x;
    if (bt >= BT) return;
    float s = 0.f;
    for (int i = 0; i < GRIDN; i++) s += g_spart[(size_t)bt * GRIDN + i];
    float raw = fminf(fmaxf(s + wtb[0], -10.f), 10.f);
    float sc  = fminf(fmaxf(softplusf_(raw), 0.1f), 10.f);
    g_scaling[bt] = sc;
    if (has_tail && (bt & (LSEQ - 1)) == (LSEQ - 1))
        dout[1048576 + (bt >> 9)] = sc;     // scaling[:, -1, :]
}

// ------------------------- B_dual -------------------------
__global__ void __launch_bounds__(256) k_bdual(
    const float* __restrict__ wc, const float* __restrict__ wtau,
    const float* __restrict__ b0, const float* __restrict__ delta)
{
    int bt = blockIdx.x;
    int lane = threadIdx.x & 31, wid = threadIdx.x >> 5;
    const float4* xc = (const float4*)(g_xconv + (size_t)bt * DI);
    for (int j = wid; j < 10; j += 8) {
        const float4* w = (const float4*)(wc + (size_t)j * DI);
        float a = 0.f;
        for (int i = lane; i < DI / 4; i += 32) {
            float4 xv = xc[i], wv = w[i];
            a += xv.x*wv.x + xv.y*wv.y + xv.z*wv.z + xv.w*wv.w;
        }
        #pragma unroll
        for (int o = 16; o; o >>= 1) a += __shfl_xor_sync(0xffffffffu, a, o);
        if (lane == 0) g_bdual[bt * 16 + j] = sigmf_(a) * b0[j];
    }
    if (wid < 6 && lane == 0) {
        float stg = delta[bt] * g_scaling[bt];
        g_bdual[bt * 16 + 10 + wid] = sigmf_(stg * wtau[wid]) * b0[10 + wid];
    }
}

// ------------------------- SSM scan + y gating -------------------------
__global__ void __launch_bounds__(256) k_scan(
    const float* __restrict__ delta, const float* __restrict__ alog,
    const float* __restrict__ dparam)
{
    int g = blockIdx.x * 256 + threadIdx.x;    // 65536 = 2*2048*16
    int n = g & 15;
    int d = (g >> 4) & (DI - 1);
    int b = g >> 15;
    float Acoef = -expf(alog[d * 16 + n]);
    float Dp = dparam[d];
    float h = 0.f, prev = 0.f;
    for (int t = 0; t < LSEQ; t++) {
        int bt = b * LSEQ + t;
        float stg = delta[bt] * g_scaling[bt];
        float itv = stg - prev; prev = stg;
        float bdt = g_basedt[(size_t)bt * DI + d];
        float dts = fminf(fmaxf(itv * bdt, 1e-6f), 10.f);
        float dA = __expf(fmaxf(dts * Acoef, -20.f));
        float xc = g_xconv[(size_t)bt * DI + d];
        float bd = g_bdual[bt * 16 + n];
        h = fmaf(dA, h, dts * bd * xc);
        float yv = h * g_xdbl[(size_t)bt * 96 + 80 + n];
        yv += __shfl_xor_sync(0xffffffffu, yv, 1);
        yv += __shfl_xor_sync(0xffffffffu, yv, 2);
        yv += __shfl_xor_sync(0xffffffffu, yv, 4);
        yv += __shfl_xor_sync(0xffffffffu, yv, 8);
        if (n == 0) {
            float z = g_xz[(size_t)bt * 4096 + 2048 + d];
            g_ygated[(size_t)bt * DI + d] = (yv + xc * Dp) * (z * sigmf_(z));
        }
    }
}

// ------------------------- launch -------------------------
extern "C" void kernel_launch(void* const* d_in, const int* in_sizes, int n_in,
                              void* d_out, int out_size)
{
    const float* x         = (const float*)d_in[0];
    const float* delta     = (const float*)d_in[1];
    const float* in_proj_w = (const float*)d_in[2];
    const float* conv_w    = (const float*)d_in[3];
    const float* conv_b    = (const float*)d_in[4];
    const float* gru_wih   = (const float*)d_in[5];
    const float* gru_whh   = (const float*)d_in[6];
    const float* gru_bih   = (const float*)d_in[7];
    const float* gru_bhh   = (const float*)d_in[8];
    const float* WT_w      = (const float*)d_in[9];
    const float* WT_b      = (const float*)d_in[10];
    const float* Wc_w      = (const float*)d_in[11];
    const float* Wtau_w    = (const float*)d_in[12];
    const float* B0        = (const float*)d_in[13];
    const float* xproj_w   = (const float*)d_in[14];
    const float* dtproj_w  = (const float*)d_in[15];
    const float* dtproj_b  = (const float*)d_in[16];
    const float* A_log     = (const float*)d_in[17];
    const float* D_param   = (const float*)d_in[18];
    const float* outproj_w = (const float*)d_in[19];
    float* out = (float*)d_out;

    float *p_xz, *p_xconv, *p_gi, *p_xdbl, *p_basedt, *p_ygated;
    cudaGetSymbolAddress((void**)&p_xz, g_xz);
    cudaGetSymbolAddress((void**)&p_xconv, g_xconv);
    cudaGetSymbolAddress((void**)&p_gi, g_gi);
    cudaGetSymbolAddress((void**)&p_xdbl, g_xdbl);
    cudaGetSymbolAddress((void**)&p_basedt, g_basedt);
    cudaGetSymbolAddress((void**)&p_ygated, g_ygated);

    const int smem_gru = (UC_S * 3 * DI + 84 * 8 + 32) * 4;   // ~199.4 KB
    cudaFuncSetAttribute(k_gru, cudaFuncAttributeMaxDynamicSharedMemorySize, smem_gru);

    k_init<<<16, 256>>>();
    // xz = x @ in_proj_w^T   (M=1024, N=4096, K=1024)
    k_gemm128<0><<<dim3(32, 8), 256>>>(x, 1024, in_proj_w, 1024, nullptr, p_xz, 4096, 1024);
    // conv + silu
    k_conv<<<(BT * DI) / 256, 256>>>(conv_w, conv_b);
    // gi = x_conv @ gru_wih^T + bih   (N=6144, K=2048)
    k_gemm128<1><<<dim3(48, 8), 256>>>(p_xconv, DI, gru_wih, DI, gru_bih, p_gi, 6144, DI);
    // x_dbl = x_conv @ xproj_w^T   (N=96, K=2048)
    k_gemm<0><<<dim3(2, 16), 256>>>(p_xconv, DI, xproj_w, DI, nullptr, p_xdbl, 96, 96, DI);
    // persistent GRU (writes h trajectory partials -> g_spart)
    k_gru<<<GRIDN, 256, smem_gru>>>(gru_whh, gru_bhh, WT_w);
    // scaling + tail output
    k_scale<<<4, 256>>>(WT_b, out, out_size >= 1048578 ? 1 : 0);
    // base_dt = softplus(dt_low @ dtproj_w^T + 2*dtproj_b)  (N=2048, K=64, lda=96)
    k_gemm<2><<<dim3(32, 16), 256>>>(p_xdbl, 96, dtproj_w, 64, dtproj_b, p_basedt, DI, DI, 64);
    // B_dual
    k_bdual<<<BT, 256>>>(Wc_w, Wtau_w, B0, delta);
    // SSM scan + gating
    k_scan<<<256, 256>>>(delta, A_log, D_param);
    // out = y_gated @ outproj_w^T   (N=1024, K=2048)
    k_gemm<0><<<dim3(16, 16), 256>>>(p_ygated, DI, outproj_w, DI, nullptr, out, 1024, 1024, DI);
}

// round 7
// speedup vs baseline: 1.5693x; 1.5693x over previous
#include <cuda_runtime.h>
#include <cuda_bf16.h>
#include <cstdint>

#define DI    2048
#define LSEQ  512
#define BT    1024          // B*L
#define GRIDN 148
#define UC_S  8             // units per block with SMEM-cached weights

// ------------------------- device scratch -------------------------
__device__ float g_xz[(size_t)BT * 4096];      // [bt][x_in(2048) | z(2048)]
__device__ float g_xconv[(size_t)BT * DI];
__device__ float g_gi[(size_t)BT * 6144];
__device__ float g_basedt[(size_t)BT * DI];
__device__ float g_ygated[(size_t)BT * DI];
__device__ float g_xdbl[(size_t)BT * 96];
__device__ float g_bdual[BT * 16];
__device__ float g_scaling[BT];
__device__ float g_spart[(size_t)BT * GRIDN];
__device__ float g_h[2][2 * DI];
__device__ unsigned g_flag[GRIDN * 32];        // one 128B line per block

__device__ __forceinline__ float sigmf_(float x) { return 1.f / (1.f + expf(-x)); }
__device__ __forceinline__ float softplusf_(float x) {
    return fmaxf(x, 0.f) + log1pf(expf(-fabsf(x)));
}

// ------------------------- init -------------------------
__global__ void k_init() {
    int i = blockIdx.x * 256 + threadIdx.x;
    if (i < 2 * DI) g_h[1][i] = 0.f;           // h(-1) read buffer
    if (i < GRIDN * 32) g_flag[i] = 0u;
}

// ------------------- 128x128 tiled GEMM: C = act(A @ W^T [+bias]) ----------
// Requires M,N % 128 == 0, K % 16 == 0.
template <int ACT>
__global__ void __launch_bounds__(256) k_gemm128(
    const float* __restrict__ A, int lda,
    const float* __restrict__ W, int ldw,
    const float* __restrict__ bias,
    float* __restrict__ C, int ldc, int K)
{
    __shared__ float As[16][132];
    __shared__ float Bs[16][132];
    int tid = threadIdx.x;
    int bm = blockIdx.y * 128, bn = blockIdx.x * 128;
    int lr = tid >> 2;               // 0..63
    int lc = (tid & 3) << 2;         // 0,4,8,12
    int ty = tid >> 4, tx = tid & 15;
    const float* A0 = A + (size_t)(bm + lr) * lda;
    const float* A1 = A + (size_t)(bm + lr + 64) * lda;
    const float* W0 = W + (size_t)(bn + lr) * ldw;
    const float* W1 = W + (size_t)(bn + lr + 64) * ldw;
    float acc[8][8] = {};
    for (int k0 = 0; k0 < K; k0 += 16) {
        float4 a0 = *(const float4*)(A0 + k0 + lc);
        float4 a1 = *(const float4*)(A1 + k0 + lc);
        float4 w0 = *(const float4*)(W0 + k0 + lc);
        float4 w1 = *(const float4*)(W1 + k0 + lc);
        __syncthreads();
        As[lc+0][lr] = a0.x; As[lc+1][lr] = a0.y; As[lc+2][lr] = a0.z; As[lc+3][lr] = a0.w;
        As[lc+0][lr+64] = a1.x; As[lc+1][lr+64] = a1.y; As[lc+2][lr+64] = a1.z; As[lc+3][lr+64] = a1.w;
        Bs[lc+0][lr] = w0.x; Bs[lc+1][lr] = w0.y; Bs[lc+2][lr] = w0.z; Bs[lc+3][lr] = w0.w;
        Bs[lc+0][lr+64] = w1.x; Bs[lc+1][lr+64] = w1.y; Bs[lc+2][lr+64] = w1.z; Bs[lc+3][lr+64] = w1.w;
        __syncthreads();
        #pragma unroll
        for (int kk = 0; kk < 16; kk++) {
            float af[8], bf[8];
            *(float4*)af       = *(const float4*)&As[kk][ty * 8];
            *(float4*)(af + 4) = *(const float4*)&As[kk][ty * 8 + 4];
            *(float4*)bf       = *(const float4*)&Bs[kk][tx * 8];
            *(float4*)(bf + 4) = *(const float4*)&Bs[kk][tx * 8 + 4];
            #pragma unroll
            for (int i = 0; i < 8; i++)
                #pragma unroll
                for (int j = 0; j < 8; j++)
                    acc[i][j] = fmaf(af[i], bf[j], acc[i][j]);
        }
    }
    #pragma unroll
    for (int i = 0; i < 8; i++) {
        size_t row = (size_t)(bm + ty * 8 + i) * ldc;
        #pragma unroll
        for (int j = 0; j < 8; j++) {
            int col = bn + tx * 8 + j;
            float v = acc[i][j];
            if (ACT == 1) v += bias[col];
            C[row + col] = v;
        }
    }
}

// --------------- small generic GEMM (64x64): C = act(A @ W^T [+bias]) ------
// ACT: 0 none, 1 +bias, 2 softplus(acc + 2*bias)
template <int ACT>
__global__ void __launch_bounds__(256) k_gemm(
    const float* __restrict__ A, int lda,
    const float* __restrict__ W, int ldw,
    const float* __restrict__ bias,
    float* __restrict__ C, int ldc, int N, int K)
{
    __shared__ float As[16][68];
    __shared__ float Bs[16][68];
    int tid = threadIdx.x;
    int bm = blockIdx.y * 64, bn = blockIdx.x * 64;
    int tx = tid & 15, ty = tid >> 4;
    int lr = tid >> 2, lk = (tid & 3) * 4;
    float acc[4][4] = {};
    for (int k0 = 0; k0 < K; k0 += 16) {
        float4 av = *(const float4*)(A + (size_t)(bm + lr) * lda + k0 + lk);
        float4 wv = make_float4(0.f, 0.f, 0.f, 0.f);
        if (bn + lr < N) wv = *(const float4*)(W + (size_t)(bn + lr) * ldw + k0 + lk);
        __syncthreads();
        As[lk][lr] = av.x; As[lk+1][lr] = av.y; As[lk+2][lr] = av.z; As[lk+3][lr] = av.w;
        Bs[lk][lr] = wv.x; Bs[lk+1][lr] = wv.y; Bs[lk+2][lr] = wv.z; Bs[lk+3][lr] = wv.w;
        __syncthreads();
        #pragma unroll
        for (int kk = 0; kk < 16; kk++) {
            float4 a = *(const float4*)&As[kk][ty * 4];
            float4 b = *(const float4*)&Bs[kk][tx * 4];
            float ar[4] = {a.x, a.y, a.z, a.w};
            float br[4] = {b.x, b.y, b.z, b.w};
            #pragma unroll
            for (int i = 0; i < 4; i++)
                #pragma unroll
                for (int j = 0; j < 4; j++)
                    acc[i][j] = fmaf(ar[i], br[j], acc[i][j]);
        }
    }
    #pragma unroll
    for (int i = 0; i < 4; i++) {
        int row = bm + ty * 4 + i;
        #pragma unroll
        for (int j = 0; j < 4; j++) {
            int col = bn + tx * 4 + j;
            if (col < N) {
                float v = acc[i][j];
                if (ACT == 1) v += bias[col];
                if (ACT == 2) { v += 2.f * bias[col]; v = softplusf_(v); }
                C[(size_t)row * ldc + col] = v;
            }
        }
    }
}

// ------------------------- causal conv + silu -------------------------
__global__ void __launch_bounds__(256) k_conv(
    const float* __restrict__ cw, const float* __restrict__ cb)
{
    int idx = blockIdx.x * 256 + threadIdx.x;     // over BT*DI
    int d = idx & (DI - 1);
    int bt = idx >> 11;
    int t = bt & (LSEQ - 1);
    float acc = cb[d];
    #pragma unroll
    for (int k = 0; k < 4; k++) {
        int tt = t + k - 3;
        if (tt >= 0)
            acc = fmaf(g_xz[(size_t)(bt + k - 3) * 4096 + d], cw[d * 4 + k], acc);
    }
    g_xconv[(size_t)bt * DI + d] = acc * sigmf_(acc);   // silu
}

// ------------------------- persistent GRU v3 -------------------------
// 148 blocks x 256 threads. Each warp owns a 256-wide k-slice of h (in regs).
// 8 units' weights in SMEM fp32; remaining <=6 units' k-slices in registers.
// Weights read exactly once per step. Padded per-block flags + nanosleep poll.
__global__ void __launch_bounds__(256, 1) k_gru(
    const float* __restrict__ whh, const float* __restrict__ bhh,
    const float* __restrict__ wtw)
{
    extern __shared__ float sm[];
    float* sw = sm;                      // UC_S*3*DI fp32 weight rows
    float* ps = sm + UC_S * 3 * DI;      // 84*8 partials [row2][warp]
    float* sc = ps + 84 * 8;             // 32 scaling partials

    int bid = blockIdx.x, tid = threadIdx.x;
    int lane = tid & 31, wid = tid >> 5;
    int ustart = bid * 13 + min(bid, 124);
    int ucnt = 13 + (bid < 124 ? 1 : 0);
    int nreg3 = (ucnt - UC_S) * 3;       // 15 or 18 register rows
    int kb = wid * 256 + lane * 4;       // this lane's chunk0 base (chunk1 = +128)

    // preload SMEM weight rows: r = u*3+g, u in [0,8)
    for (int r = 0; r < UC_S * 3; r++) {
        int u = r / 3, g = r - u * 3;
        const float4* src = (const float4*)(whh + ((size_t)g * DI + ustart + u) * DI);
        float4* dst = (float4*)(sw + r * DI);
        for (int i = tid; i < DI / 4; i += 256) dst[i] = src[i];
    }
    // preload register weight rows: rr -> u = UC_S + rr/3, g = rr%3
    float wr[18][8] = {};
    #pragma unroll
    for (int rr = 0; rr < 18; rr++) {
        if (rr < nreg3) {
            int u = UC_S + rr / 3, g = rr - (rr / 3) * 3;
            const float* base = whh + ((size_t)g * DI + ustart + u) * DI;
            float4 c0 = *(const float4*)(base + kb);
            float4 c1 = *(const float4*)(base + kb + 128);
            wr[rr][0] = c0.x; wr[rr][1] = c0.y; wr[rr][2] = c0.z; wr[rr][3] = c0.w;
            wr[rr][4] = c1.x; wr[rr][5] = c1.y; wr[rr][6] = c1.z; wr[rr][7] = c1.w;
        }
    }
    // epilogue constants (one thread per (u,b))
    float eb_r = 0.f, eb_z = 0.f, eb_n = 0.f, ewt = 0.f;
    if (tid < 2 * ucnt) {
        int d = ustart + (tid >> 1);
        eb_r = bhh[d]; eb_z = bhh[2048 + d]; eb_n = bhh[4096 + d]; ewt = wtw[d];
    }
    __syncthreads();

    for (int t = 0; t < LSEQ; t++) {
        if (t > 0) {
            if (tid < GRIDN) {
                volatile unsigned* f = (volatile unsigned*)&g_flag[tid * 32];
                while (*f < (unsigned)t) { __nanosleep(64); }
            }
            __syncthreads();
        }
        const float* hp = g_h[(t + 1) & 1];

        // load this warp's h slice into registers (L2-coherent)
        float h0[8], h1[8];
        {
            float4 a = __ldcg((const float4*)(hp + kb));
            float4 b = __ldcg((const float4*)(hp + kb + 128));
            h0[0]=a.x; h0[1]=a.y; h0[2]=a.z; h0[3]=a.w;
            h0[4]=b.x; h0[5]=b.y; h0[6]=b.z; h0[7]=b.w;
            float4 c = __ldcg((const float4*)(hp + DI + kb));
            float4 d4 = __ldcg((const float4*)(hp + DI + kb + 128));
            h1[0]=c.x; h1[1]=c.y; h1[2]=c.z; h1[3]=c.w;
            h1[4]=d4.x; h1[5]=d4.y; h1[6]=d4.z; h1[7]=d4.w;
        }
        // epilogue inputs prefetch (hidden under dot compute)
        float gi_r = 0.f, gi_z = 0.f, gi_n = 0.f, hprev = 0.f;
        if (tid < 2 * ucnt) {
            int u = tid >> 1, b = tid & 1, d = ustart + u;
            size_t gib = ((size_t)(b * LSEQ + t)) * 6144 + d;
            gi_r = __ldg(&g_gi[gib]);
            gi_z = __ldg(&g_gi[gib + 2048]);
            gi_n = __ldg(&g_gi[gib + 4096]);
            hprev = __ldcg(&hp[b * DI + d]);
        }

        // --- dot products: SMEM rows ---
        bool lo = lane < 16;
        for (int r = 0; r < UC_S * 3; r++) {
            const float* w = sw + r * DI + kb;
            float4 w0 = *(const float4*)w;
            float4 w1 = *(const float4*)(w + 128);
            float a0, a1;
            a0  = w0.x * h0[0]; a1  = w0.x * h1[0];
            a0 = fmaf(w0.y, h0[1], a0); a1 = fmaf(w0.y, h1[1], a1);
            a0 = fmaf(w0.z, h0[2], a0); a1 = fmaf(w0.z, h1[2], a1);
            a0 = fmaf(w0.w, h0[3], a0); a1 = fmaf(w0.w, h1[3], a1);
            a0 = fmaf(w1.x, h0[4], a0); a1 = fmaf(w1.x, h1[4], a1);
            a0 = fmaf(w1.y, h0[5], a0); a1 = fmaf(w1.y, h1[5], a1);
            a0 = fmaf(w1.z, h0[6], a0); a1 = fmaf(w1.z, h1[6], a1);
            a0 = fmaf(w1.w, h0[7], a0); a1 = fmaf(w1.w, h1[7], a1);
            // fold both accs into one butterfly: lanes<16 reduce a0, lanes>=16 reduce a1
            float v = (lo ? a0 : a1) + __shfl_xor_sync(0xffffffffu, lo ? a1 : a0, 16);
            v += __shfl_xor_sync(0xffffffffu, v, 8);
            v += __shfl_xor_sync(0xffffffffu, v, 4);
            v += __shfl_xor_sync(0xffffffffu, v, 2);
            v += __shfl_xor_sync(0xffffffffu, v, 1);
            if ((lane & 15) == 0) ps[(r * 2 + (lane >> 4)) * 8 + wid] = v;
        }
        // --- dot products: register rows ---
        #pragma unroll
        for (int rr = 0; rr < 18; rr++) {
            if (rr < nreg3) {
                float a0 = 0.f, a1 = 0.f;
                #pragma unroll
                for (int j = 0; j < 8; j++) {
                    a0 = fmaf(wr[rr][j], h0[j], a0);
                    a1 = fmaf(wr[rr][j], h1[j], a1);
                }
                float v = (lo ? a0 : a1) + __shfl_xor_sync(0xffffffffu, lo ? a1 : a0, 16);
                v += __shfl_xor_sync(0xffffffffu, v, 8);
                v += __shfl_xor_sync(0xffffffffu, v, 4);
                v += __shfl_xor_sync(0xffffffffu, v, 2);
                v += __shfl_xor_sync(0xffffffffu, v, 1);
                if ((lane & 15) == 0) ps[((UC_S * 3 + rr) * 2 + (lane >> 4)) * 8 + wid] = v;
            }
        }
        __syncthreads();

        // --- epilogue: one thread per (u,b) ---
        if (tid < 2 * ucnt) {
            int u = tid >> 1, b = tid & 1, d = ustart + u;
            int r0 = (u * 3 + 0) * 2 + b;
            int r1 = (u * 3 + 1) * 2 + b;
            int r2 = (u * 3 + 2) * 2 + b;
            float hr = 0.f, hz = 0.f, hn = 0.f;
            #pragma unroll
            for (int w = 0; w < 8; w++) {
                hr += ps[r0 * 8 + w];
                hz += ps[r1 * 8 + w];
                hn += ps[r2 * 8 + w];
            }
            float r  = sigmf_(gi_r + hr + eb_r);
            float uz = sigmf_(gi_z + hz + eb_z);
            float nn = tanhf (gi_n + r * (hn + eb_n));
            float hnew = (1.f - uz) * nn + uz * hprev;
            __stcg(&g_h[t & 1][b * DI + d], hnew);
            sc[tid] = hnew * ewt;
            __threadfence();
        }
        __syncthreads();
        if (tid == 0) __stcg(&g_flag[bid * 32], (unsigned)(t + 1));   // release ASAP
        if (tid < 2) {                                                // off critical path
            float s = 0.f;
            for (int u = 0; u < ucnt; u++) s += sc[u * 2 + tid];
            g_spart[((size_t)(tid * LSEQ + t)) * GRIDN + bid] = s;
        }
    }
}

// ------------------------- scaling reduce (deterministic) -------------------
__global__ void k_scale(const float* __restrict__ wtb, float* __restrict__ dout,
                        int has_tail)
{
    int bt = blockIdx.x * blockDim.x + threadIdx.x;
    if (bt >= BT) return;
    float s = 0.f;
    for (int i = 0; i < GRIDN; i++) s += g_spart[(size_t)bt * GRIDN + i];
    float raw = fminf(fmaxf(s + wtb[0], -10.f), 10.f);
    float sc  = fminf(fmaxf(softplusf_(raw), 0.1f), 10.f);
    g_scaling[bt] = sc;
    if (has_tail && (bt & (LSEQ - 1)) == (LSEQ - 1))
        dout[1048576 + (bt >> 9)] = sc;     // scaling[:, -1, :]
}

// ------------------------- B_dual -------------------------
__global__ void __launch_bounds__(256) k_bdual(
    const float* __restrict__ wc, const float* __restrict__ wtau,
    const float* __restrict__ b0, const float* __restrict__ delta)
{
    int bt = blockIdx.x;
    int lane = threadIdx.x & 31, wid = threadIdx.x >> 5;
    const float4* xc = (const float4*)(g_xconv + (size_t)bt * DI);
    for (int j = wid; j < 10; j += 8) {
        const float4* w = (const float4*)(wc + (size_t)j * DI);
        float a = 0.f;
        for (int i = lane; i < DI / 4; i += 32) {
            float4 xv = xc[i], wv = w[i];
            a += xv.x*wv.x + xv.y*wv.y + xv.z*wv.z + xv.w*wv.w;
        }
        #pragma unroll
        for (int o = 16; o; o >>= 1) a += __shfl_xor_sync(0xffffffffu, a, o);
        if (lane == 0) g_bdual[bt * 16 + j] = sigmf_(a) * b0[j];
    }
    if (wid < 6 && lane == 0) {
        float stg = delta[bt] * g_scaling[bt];
        g_bdual[bt * 16 + 10 + wid] = sigmf_(stg * wtau[wid]) * b0[10 + wid];
    }
}

// ------------------------- SSM scan + y gating -------------------------
__global__ void __launch_bounds__(256) k_scan(
    const float* __restrict__ delta, const float* __restrict__ alog,
    const float* __restrict__ dparam)
{
    int g = blockIdx.x * 256 + threadIdx.x;    // 65536 = 2*2048*16
    int n = g & 15;
    int d = (g >> 4) & (DI - 1);
    int b = g >> 15;
    float Acoef = -expf(alog[d * 16 + n]);
    float Dp = dparam[d];
    float h = 0.f, prev = 0.f;
    for (int t = 0; t < LSEQ; t++) {
        int bt = b * LSEQ + t;
        float stg = delta[bt] * g_scaling[bt];
        float itv = stg - prev; prev = stg;
        float bdt = g_basedt[(size_t)bt * DI + d];
        float dts = fminf(fmaxf(itv * bdt, 1e-6f), 10.f);
        float dA = __expf(fmaxf(dts * Acoef, -20.f));
        float xc = g_xconv[(size_t)bt * DI + d];
        float bd = g_bdual[bt * 16 + n];
        h = fmaf(dA, h, dts * bd * xc);
        float yv = h * g_xdbl[(size_t)bt * 96 + 80 + n];
        yv += __shfl_xor_sync(0xffffffffu, yv, 1);
        yv += __shfl_xor_sync(0xffffffffu, yv, 2);
        yv += __shfl_xor_sync(0xffffffffu, yv, 4);
        yv += __shfl_xor_sync(0xffffffffu, yv, 8);
        if (n == 0) {
            float z = g_xz[(size_t)bt * 4096 + 2048 + d];
            g_ygated[(size_t)bt * DI + d] = (yv + xc * Dp) * (z * sigmf_(z));
        }
    }
}

// ------------------------- launch -------------------------
extern "C" void kernel_launch(void* const* d_in, const int* in_sizes, int n_in,
                              void* d_out, int out_size)
{
    const float* x         = (const float*)d_in[0];
    const float* delta     = (const float*)d_in[1];
    const float* in_proj_w = (const float*)d_in[2];
    const float* conv_w    = (const float*)d_in[3];
    const float* conv_b    = (const float*)d_in[4];
    const float* gru_wih   = (const float*)d_in[5];
    const float* gru_whh   = (const float*)d_in[6];
    const float* gru_bih   = (const float*)d_in[7];
    const float* gru_bhh   = (const float*)d_in[8];
    const float* WT_w      = (const float*)d_in[9];
    const float* WT_b      = (const float*)d_in[10];
    const float* Wc_w      = (const float*)d_in[11];
    const float* Wtau_w    = (const float*)d_in[12];
    const float* B0        = (const float*)d_in[13];
    const float* xproj_w   = (const float*)d_in[14];
    const float* dtproj_w  = (const float*)d_in[15];
    const float* dtproj_b  = (const float*)d_in[16];
    const float* A_log     = (const float*)d_in[17];
    const float* D_param   = (const float*)d_in[18];
    const float* outproj_w = (const float*)d_in[19];
    float* out = (float*)d_out;

    float *p_xz, *p_xconv, *p_gi, *p_xdbl, *p_basedt, *p_ygated;
    cudaGetSymbolAddress((void**)&p_xz, g_xz);
    cudaGetSymbolAddress((void**)&p_xconv, g_xconv);
    cudaGetSymbolAddress((void**)&p_gi, g_gi);
    cudaGetSymbolAddress((void**)&p_xdbl, g_xdbl);
    cudaGetSymbolAddress((void**)&p_basedt, g_basedt);
    cudaGetSymbolAddress((void**)&p_ygated, g_ygated);

    const int smem_gru = (UC_S * 3 * DI + 84 * 8 + 32) * 4;   // ~199.4 KB
    cudaFuncSetAttribute(k_gru, cudaFuncAttributeMaxDynamicSharedMemorySize, smem_gru);

    k_init<<<32, 256>>>();
    // xz = x @ in_proj_w^T   (M=1024, N=4096, K=1024)
    k_gemm128<0><<<dim3(32, 8), 256>>>(x, 1024, in_proj_w, 1024, nullptr, p_xz, 4096, 1024);
    // conv + silu
    k_conv<<<(BT * DI) / 256, 256>>>(conv_w, conv_b);
    // gi = x_conv @ gru_wih^T + bih   (N=6144, K=2048)
    k_gemm128<1><<<dim3(48, 8), 256>>>(p_xconv, DI, gru_wih, DI, gru_bih, p_gi, 6144, DI);
    // x_dbl = x_conv @ xproj_w^T   (N=96, K=2048)
    k_gemm<0><<<dim3(2, 16), 256>>>(p_xconv, DI, xproj_w, DI, nullptr, p_xdbl, 96, 96, DI);
    // persistent GRU (writes h trajectory partials -> g_spart)
    k_gru<<<GRIDN, 256, smem_gru>>>(gru_whh, gru_bhh, WT_w);
    // scaling + tail output
    k_scale<<<4, 256>>>(WT_b, out, out_size >= 1048578 ? 1 : 0);
    // base_dt = softplus(dt_low @ dtproj_w^T + 2*dtproj_b)  (N=2048, K=64, lda=96)
    k_gemm<2><<<dim3(32, 16), 256>>>(p_xdbl, 96, dtproj_w, 64, dtproj_b, p_basedt, DI, DI, 64);
    // B_dual
    k_bdual<<<BT, 256>>>(Wc_w, Wtau_w, B0, delta);
    // SSM scan + gating
    k_scan<<<256, 256>>>(delta, A_log, D_param);
    // out = y_gated @ outproj_w^T   (N=1024, K=2048)
    k_gemm<0><<<dim3(16, 16), 256>>>(p_ygated, DI, outproj_w, DI, nullptr, out, 1024, 1024, DI);
}